// round 13
// baseline (speedup 1.0000x reference)
#include <cuda_runtime.h>
#include <cuda_fp16.h>
#include <cstdint>
#include <cstddef>

#define B_     64
#define T_     512
#define D_     1024
#define U_     1024
#define G_     4128
#define GP_    4224
#define NT_    33           // GP_/128 col tiles for k_xw
#define NTM_   256          // MR_/128 row tiles for k_xw
#define MR_    32768        // B_*T_
#define NBK_   128          // recurrent blocks (no master block)

// ---------------- static device scratch (no allocation APIs) ----------------
__device__ __align__(256) uint4 g_xq[(size_t)NTM_ * 16384]; // x fp16 A-frag quads
__device__ __align__(256) uint4 g_wq[(size_t)NT_ * 16384];  // W fp16 B-frag quads
__device__ __align__(256) uint4 g_bq[(size_t)NBK_ * 8192];  // R fp16 B-frag quads (64 cols/blk)
__device__ __align__(256) uint4 g_hq[2][8192];              // h fp16 A-frag quads, ping-pong
__device__ __align__(256) float g_bp[GP_];                  // padded bias
__device__ __align__(256) float g_xk[(size_t)MR_ * GP_];    // x@W + bias (f32)
__device__ unsigned g_gf[8];                                 // per-chunk group flags

// ---------------- helpers ----------------------------------------------------
__device__ __forceinline__ unsigned pack2(float lo, float hi) {
    __half2 h = __floats2half2_rn(lo, hi);
    return *reinterpret_cast<unsigned*>(&h);
}
__device__ __forceinline__ void mma_f16(float c[4], unsigned a0, unsigned a1,
                                        unsigned a2, unsigned a3,
                                        unsigned b0, unsigned b1) {
    asm volatile(
        "mma.sync.aligned.m16n8k16.row.col.f32.f16.f16.f32 "
        "{%0,%1,%2,%3},{%4,%5,%6,%7},{%8,%9},{%0,%1,%2,%3};"
        : "+f"(c[0]), "+f"(c[1]), "+f"(c[2]), "+f"(c[3])
        : "r"(a0), "r"(a1), "r"(a2), "r"(a3), "r"(b0), "r"(b1));
}
__device__ __forceinline__ void cp16(void* s, const void* g) {
    unsigned a = (unsigned)__cvta_generic_to_shared(s);
    asm volatile("cp.async.cg.shared.global [%0], [%1], 16;" :: "r"(a), "l"(g));
}
__device__ __forceinline__ void cpcommit() { asm volatile("cp.async.commit_group;"); }
template<int N> __device__ __forceinline__ void cpwait() {
    asm volatile("cp.async.wait_group %0;" :: "n"(N));
}
// warp-local gate: chunk j of step t is ready (blocks 16j..16j+15 done step t-1)
__device__ __forceinline__ void gate_chunk(int j, int t, int lane) {
    if (lane == 0) {
        unsigned target = 16u * (unsigned)t;
        while (((volatile unsigned*)g_gf)[j] < target) __nanosleep(20);
    }
    __syncwarp();
}

// ---------------- prepack kernels (layouts identical to R12) ------------------
__global__ void k_pack_xq(const float* __restrict__ x) {
    size_t qid = (size_t)blockIdx.x * blockDim.x + threadIdx.x;
    if (qid >= (size_t)NTM_ * 16384) return;
    int tile = (int)(qid >> 14);
    int rem  = (int)(qid & 16383);
    int ku   = rem >> 8;
    int mgrp = (rem >> 5) & 7;
    int lane = rem & 31;
    int grp = lane >> 2, tig = lane & 3;
    int r0 = tile * 128 + mgrp * 16 + grp;
    int k0 = ku * 16 + 2 * tig;
    const float* x0 = x + (size_t)r0 * D_;
    const float* x1 = x0 + (size_t)8 * D_;
    uint4 q;
    q.x = pack2(x0[k0],     x0[k0 + 1]);
    q.y = pack2(x1[k0],     x1[k0 + 1]);
    q.z = pack2(x0[k0 + 8], x0[k0 + 9]);
    q.w = pack2(x1[k0 + 8], x1[k0 + 9]);
    g_xq[qid] = q;
}

__global__ void k_pack_wq(const float* __restrict__ W, const float* __restrict__ bias) {
    size_t qid = (size_t)blockIdx.x * blockDim.x + threadIdx.x;
    if (qid < (size_t)NT_ * 16384) {
        int nt  = (int)(qid >> 14);
        int rem = (int)(qid & 16383);
        int ku2 = rem >> 9;
        int ng  = (rem >> 5) & 15;
        int lane = rem & 31;
        int grp = lane >> 2, tig = lane & 3;
        int col = nt * 128 + ng * 8 + grp;
        int kb = ku2 * 32 + 2 * tig;
        uint4 q;
        if (col < G_) {
            const float* Wc = W + col;
            q.x = pack2(Wc[(size_t)(kb)      * G_], Wc[(size_t)(kb + 1)  * G_]);
            q.y = pack2(Wc[(size_t)(kb + 8)  * G_], Wc[(size_t)(kb + 9)  * G_]);
            q.z = pack2(Wc[(size_t)(kb + 16) * G_], Wc[(size_t)(kb + 17) * G_]);
            q.w = pack2(Wc[(size_t)(kb + 24) * G_], Wc[(size_t)(kb + 25) * G_]);
        } else {
            q = make_uint4(0u, 0u, 0u, 0u);
        }
        g_wq[qid] = q;
    }
    if (qid < GP_) g_bp[qid] = ((int)qid < G_) ? bias[qid] : 0.f;
}

__global__ void k_pack_rq(const float* __restrict__ R) {
    int qid = blockIdx.x * 256 + threadIdx.x;
    if (qid >= NBK_ * 8192) return;
    int bk  = qid >> 13;
    int rem = qid & 8191;
    int ku2 = rem >> 8;
    int col = (rem >> 2) & 63;
    int tig = rem & 3;
    int sc = (col < 32) ? (32 + (col >> 3) * 1024 + bk * 8 + (col & 7)) : (col - 32);
    int kb = ku2 * 32 + 2 * tig;
    const float* Rc = R + sc;
    uint4 q;
    q.x = pack2(Rc[(size_t)(kb)      * G_], Rc[(size_t)(kb + 1)  * G_]);
    q.y = pack2(Rc[(size_t)(kb + 8)  * G_], Rc[(size_t)(kb + 9)  * G_]);
    q.z = pack2(Rc[(size_t)(kb + 16) * G_], Rc[(size_t)(kb + 17) * G_]);
    q.w = pack2(Rc[(size_t)(kb + 24) * G_], Rc[(size_t)(kb + 25) * G_]);
    g_bq[(size_t)bk * 8192 + rem] = q;
}

__global__ void k_zero() {
    int i = blockIdx.x * blockDim.x + threadIdx.x;
    if (i < 8192) g_hq[0][i] = make_uint4(0u, 0u, 0u, 0u);
    if (i < 8) g_gf[i] = 0u;
}

// ---------------- precompute GEMM: g_xk = x @ W + bias (fp16 mma) -------------
__global__ __launch_bounds__(256, 2) void k_xw() {
    extern __shared__ uint4 sm4[];
    uint4* As4 = sm4;          // [2][1024]
    uint4* Bs4 = sm4 + 2048;   // [2][1024]

    const int tid  = threadIdx.x;
    const int warp = tid >> 5, lane = tid & 31;
    const int grp  = lane >> 2, tig = lane & 3;
    const int wMg  = (warp >> 1) * 2;
    const int wNg  = (warp & 1) * 8;
    const int nt_blk = blockIdx.x;
    const size_t row0 = (size_t)blockIdx.y * 128;

    const uint4* Asrc = g_xq + (size_t)blockIdx.y * 16384;
    const uint4* Bsrc = g_wq + (size_t)nt_blk * 16384;

    auto load_chunk = [&](int kc, int buf) {
        const uint4* as = Asrc + kc * 1024;
        const uint4* bs = Bsrc + kc * 1024;
        uint4* ad = As4 + buf * 1024;
        uint4* bd = Bs4 + buf * 1024;
        #pragma unroll
        for (int r = 0; r < 4; r++) cp16(ad + tid + r * 256, as + tid + r * 256);
        #pragma unroll
        for (int r = 0; r < 4; r++) cp16(bd + tid + r * 256, bs + tid + r * 256);
        cpcommit();
    };

    load_chunk(0, 0);

    float acc[2][8][4];
    #pragma unroll
    for (int a = 0; a < 2; a++)
        #pragma unroll
        for (int b = 0; b < 8; b++)
            #pragma unroll
            for (int c = 0; c < 4; c++) acc[a][b][c] = 0.f;

    for (int kc = 0; kc < 16; ++kc) {
        if (kc < 15) { load_chunk(kc + 1, (kc + 1) & 1); cpwait<1>(); }
        else         { cpwait<0>(); }
        __syncthreads();
        const uint4* A = As4 + (kc & 1) * 1024;
        const uint4* B = Bs4 + (kc & 1) * 1024;
        #pragma unroll
        for (int ku2l = 0; ku2l < 2; ku2l++) {
            #pragma unroll
            for (int par = 0; par < 2; par++) {
                int kul = ku2l * 2 + par;
                uint4 a0q = A[kul * 256 + wMg * 32 + lane];
                uint4 a1q = A[kul * 256 + (wMg + 1) * 32 + lane];
                #pragma unroll
                for (int nt = 0; nt < 8; nt++) {
                    uint4 bq = B[ku2l * 512 + (wNg + nt) * 32 + lane];
                    unsigned b0 = par ? bq.z : bq.x;
                    unsigned b1 = par ? bq.w : bq.y;
                    mma_f16(acc[0][nt], a0q.x, a0q.y, a0q.z, a0q.w, b0, b1);
                    mma_f16(acc[1][nt], a1q.x, a1q.y, a1q.z, a1q.w, b0, b1);
                }
            }
        }
        __syncthreads();
    }

    const int colbase = nt_blk * 128 + (warp & 1) * 64;
    const int wM = (warp >> 1) * 32;
    #pragma unroll
    for (int nt = 0; nt < 8; nt++) {
        int gc = colbase + nt * 8 + 2 * tig;
        float bv0 = g_bp[gc], bv1 = g_bp[gc + 1];
        #pragma unroll
        for (int mt = 0; mt < 2; mt++) {
            size_t gr = row0 + wM + mt * 16 + grp;
            size_t base = gr * GP_ + gc;
            g_xk[base]     = acc[mt][nt][0] + bv0;
            g_xk[base + 1] = acc[mt][nt][1] + bv1;
            size_t base2 = base + (size_t)8 * GP_;
            g_xk[base2]     = acc[mt][nt][2] + bv0;
            g_xk[base2 + 1] = acc[mt][nt][3] + bv1;
        }
    }
}

// ---------------- persistent recurrent kernel (masterless, deep pipeline) -----
// smem: Bs 8192u4 (128KB) | As ring 4x1024u4 (64KB) | xs 64x68f | zs 64x68f | fms/ims
#define ZST 68
__global__ __launch_bounds__(256, 1) void k_rec(float* __restrict__ out) {
    extern __shared__ uint4 sm4[];
    uint4* Bs = sm4;                         // 8192
    uint4* As = sm4 + 8192;                  // 4 x 1024 ring
    float* xs  = (float*)(sm4 + 8192 + 4096);
    float* zs  = xs + 64 * ZST;
    float* fms = zs + 64 * ZST;              // 64
    float* ims = fms + 64;                   // 64

    const int tid  = threadIdx.x;
    const int bk   = blockIdx.x;
    const int warp = tid >> 5, lane = tid & 31;
    const int grp  = lane >> 2, tig = lane & 3;
    const int mg   = warp & 3;               // row group: rows mg*16..mg*16+15
    const int colbase = (warp >> 2) * 32;    // 0 = z gates, 32 = master logits
    const int u0   = bk * 8;
    const int lvl  = bk >> 3;

    // epilogue thread mapping (tid < 128) + register cell state
    const int ebg = tid >> 5, eln = tid & 31;
    const int egp = eln >> 2, etg = eln & 3;
    const int er  = ebg * 16 + egp;          // batch row
    const int ej0 = 2 * etg;                 // unit offset
    float creg[4] = {0.f, 0.f, 0.f, 0.f};

    // one-time: R frags -> smem
    {
        const uint4* bsrc = g_bq + (size_t)bk * 8192;
        #pragma unroll
        for (int r = 0; r < 32; r++) cp16(Bs + tid + r * 256, bsrc + tid + r * 256);
        cpcommit(); cpwait<0>();
        __syncthreads();
    }

    for (int t = 0; t < T_; ++t) {
        const uint4* hsrc = g_hq[t & 1];

        // group 0: xk tile (precomputed — no gating)
        {
            #pragma unroll
            for (int r = 0; r < 2; r++) {           // z gates part
                int id = tid + r * 256;
                int b = id >> 3, sub = id & 7;
                int q = sub >> 1, half = sub & 1;
                cp16(xs + b * ZST + q * 8 + half * 4,
                     g_xk + ((size_t)(b * T_ + t)) * GP_ + 32 + q * 1024 + u0 + half * 4);
            }
            #pragma unroll
            for (int r = 0; r < 2; r++) {           // master logits part
                int id = tid + r * 256;
                int b = id >> 3, cc = id & 7;
                cp16(xs + b * ZST + 32 + cc * 4,
                     g_xk + ((size_t)(b * T_ + t)) * GP_ + cc * 4);
            }
            cpcommit();
        }

        // groups 1..3: h chunks 0,1,2 (gated per warp, per chunk)
        #pragma unroll
        for (int j = 0; j < 3; j++) {
            gate_chunk(j, t, lane);
            const uint4* src = hsrc + j * 1024;
            uint4* dst = As + j * 1024;
            #pragma unroll
            for (int r = 0; r < 4; r++) cp16(dst + tid + r * 256, src + tid + r * 256);
            cpcommit();
        }

        float acc[4][4];
        #pragma unroll
        for (int a = 0; a < 4; a++)
            #pragma unroll
            for (int c = 0; c < 4; c++) acc[a][c] = 0.f;

        #pragma unroll 1
        for (int c = 0; c < 8; ++c) {
            if (c <= 5)      cpwait<2>();
            else if (c == 6) cpwait<1>();
            else             cpwait<0>();
            __syncthreads();
            if (c < 5) {
                int j = c + 3;
                gate_chunk(j, t, lane);
                const uint4* src = hsrc + j * 1024;
                uint4* dst = As + (j & 3) * 1024;
                #pragma unroll
                for (int r = 0; r < 4; r++) cp16(dst + tid + r * 256, src + tid + r * 256);
                cpcommit();
            }
            const uint4* A = As + (c & 3) * 1024;
            #pragma unroll
            for (int ku2l = 0; ku2l < 4; ++ku2l) {
                uint4 aE = A[(2 * ku2l)     * 128 + mg * 32 + lane];
                uint4 aO = A[(2 * ku2l + 1) * 128 + mg * 32 + lane];
                int ku2 = c * 4 + ku2l;
                #pragma unroll
                for (int nt = 0; nt < 4; nt++) {
                    int col = colbase + nt * 8 + grp;
                    uint4 bq = Bs[ku2 * 256 + col * 4 + tig];
                    mma_f16(acc[nt], aE.x, aE.y, aE.z, aE.w, bq.x, bq.y);
                    mma_f16(acc[nt], aO.x, aO.y, aO.z, aO.w, bq.z, bq.w);
                }
            }
        }

        // z = acc + xk -> zs
        {
            int r0 = mg * 16 + grp;
            #pragma unroll
            for (int nt = 0; nt < 4; nt++) {
                int c0 = colbase + nt * 8 + tig * 2;
                zs[r0 * ZST + c0]           = acc[nt][0] + xs[r0 * ZST + c0];
                zs[r0 * ZST + c0 + 1]       = acc[nt][1] + xs[r0 * ZST + c0 + 1];
                zs[(r0 + 8) * ZST + c0]     = acc[nt][2] + xs[(r0 + 8) * ZST + c0];
                zs[(r0 + 8) * ZST + c0 + 1] = acc[nt][3] + xs[(r0 + 8) * ZST + c0 + 1];
            }
        }
        __syncthreads();

        // local cumsoftmax at this block's level
        if (tid < 128) {
            int b = tid >> 1, half = tid & 1;
            const float* lz = zs + b * ZST + 32 + half * 16;
            float v[16], mx = -1e30f;
            #pragma unroll
            for (int i = 0; i < 16; i++) { v[i] = lz[i]; mx = fmaxf(mx, v[i]); }
            float s = 0.f;
            #pragma unroll
            for (int i = 0; i < 16; i++) { v[i] = expf(v[i] - mx); s += v[i]; }
            float p = 0.f;
            if (half == 0) {
                for (int i = 0; i <= lvl; i++) p += v[i];
                fms[b] = p / s;
            } else {
                for (int i = lvl; i < 16; i++) p += v[i];
                ims[b] = p / s;
            }
        }
        __syncthreads();

        // epilogue: gates, cell update (register state), h + out write
        uint4* hout4 = g_hq[(t + 1) & 1];
        if (tid < 128) {
            float fmA = fms[er],     imA = ims[er];
            float fmB = fms[er + 8], imB = ims[er + 8];
            float hv[4];
            #pragma unroll
            for (int e = 0; e < 4; e++) {
                int row = er + ((e >> 1) ? 8 : 0);
                int j = ej0 + (e & 1);
                float fm = (e >> 1) ? fmB : fmA;
                float im = (e >> 1) ? imB : imA;
                float fz = zs[row * ZST + j];
                float iz = zs[row * ZST + 8 + j];
                float oz = zs[row * ZST + 16 + j];
                float gz = zs[row * ZST + 24 + j];
                float f = 1.f / (1.f + expf(-fz));
                float i = 1.f / (1.f + expf(-iz));
                float o = 1.f / (1.f + expf(-oz));
                float g = tanhf(gz);
                float cp = creg[e];
                float w = fm * im;
                float c = w * (f * cp + i * g) + (fm - w) * cp + (im - w) * g;
                creg[e] = c;
                hv[e] = o * tanhf(c);
            }
            float2 o0 = make_float2(hv[0], hv[1]);
            float2 o1 = make_float2(hv[2], hv[3]);
            *(float2*)&out[((size_t)er * T_ + t) * U_ + u0 + ej0] = o0;
            *(float2*)&out[((size_t)(er + 8) * T_ + t) * U_ + u0 + ej0] = o1;
            unsigned w0 = pack2(hv[0], hv[1]);
            unsigned w1 = pack2(hv[2], hv[3]);
            char* dst = (char*)(hout4 + (bk >> 1) * 128 + ebg * 32 + eln) + (bk & 1) * 8;
            asm volatile("st.global.cg.v2.u32 [%0], {%1,%2};"
                         :: "l"(dst), "r"(w0), "r"(w1) : "memory");
        }
        __threadfence();
        __syncthreads();
        if (tid == 0) atomicAdd(&g_gf[bk >> 4], 1u);
    }
}

// ---------------- entry -------------------------------------------------------
extern "C" void kernel_launch(void* const* d_in, const int* in_sizes, int n_in,
                              void* d_out, int out_size) {
    const float* x    = (const float*)d_in[0];
    const float* W    = (const float*)d_in[1];
    const float* R    = (const float*)d_in[2];
    const float* bias = (const float*)d_in[3];
    float* out = (float*)d_out;

    // k_rec smem: 131072 + 65536 + 17408*2 + 512 = 231936
    cudaFuncSetAttribute(k_xw,  cudaFuncAttributeMaxDynamicSharedMemorySize, 65536);
    cudaFuncSetAttribute(k_rec, cudaFuncAttributeMaxDynamicSharedMemorySize, 231936);

    k_pack_xq<<<(int)(((size_t)NTM_ * 16384 + 255) / 256), 256>>>(x);
    k_pack_wq<<<(int)(((size_t)NT_ * 16384 + 255) / 256), 256>>>(W, bias);
    k_pack_rq<<<(NBK_ * 8192 + 255) / 256, 256>>>(R);
    k_zero<<<32, 256>>>();
    k_xw<<<dim3(NT_, NTM_), 256, 65536>>>();
    k_rec<<<NBK_, 256, 231936>>>(out);
}

// round 14
// speedup vs baseline: 1.4311x; 1.4311x over previous
#include <cuda_runtime.h>
#include <cuda_fp16.h>
#include <cstdint>
#include <cstddef>

#define B_     64
#define T_     512
#define D_     1024
#define U_     1024
#define G_     4128
#define NUB_   128          // unit blocks
#define NB_    129          // + 1 master block
#define ZST    68

// ---------------- static device scratch (no allocation APIs) ----------------
__device__ __align__(256) uint4 g_xtq[(size_t)T_ * 8192]; // x A-frag quads, per-step
__device__ __align__(256) uint4 g_bq[(size_t)NB_ * 8192]; // [W;R] B-frag quads per block
__device__ __align__(256) uint4 g_hq[2][8192];            // h A-frag quads, ping-pong
__device__ __align__(256) float g_masters[B_ * 32];
__device__ unsigned g_ctr;
__device__ unsigned g_mflag;

// ---------------- helpers ----------------------------------------------------
__device__ __forceinline__ unsigned pack2(float lo, float hi) {
    __half2 h = __floats2half2_rn(lo, hi);
    return *reinterpret_cast<unsigned*>(&h);
}
__device__ __forceinline__ void mma_f16(float c[4], unsigned a0, unsigned a1,
                                        unsigned a2, unsigned a3,
                                        unsigned b0, unsigned b1) {
    asm volatile(
        "mma.sync.aligned.m16n8k16.row.col.f32.f16.f16.f32 "
        "{%0,%1,%2,%3},{%4,%5,%6,%7},{%8,%9},{%0,%1,%2,%3};"
        : "+f"(c[0]), "+f"(c[1]), "+f"(c[2]), "+f"(c[3])
        : "r"(a0), "r"(a1), "r"(a2), "r"(a3), "r"(b0), "r"(b1));
}
__device__ __forceinline__ void cp16(void* s, const void* g) {
    unsigned a = (unsigned)__cvta_generic_to_shared(s);
    asm volatile("cp.async.cg.shared.global [%0], [%1], 16;" :: "r"(a), "l"(g));
}
__device__ __forceinline__ void cpcommit() { asm volatile("cp.async.commit_group;"); }
template<int N> __device__ __forceinline__ void cpwait() {
    asm volatile("cp.async.wait_group %0;" :: "n"(N));
}

// ---------------- prepack kernels (layouts identical to R6) -------------------
__global__ void k_pack_aq(const float* __restrict__ x) {
    size_t qid = (size_t)blockIdx.x * 256 + threadIdx.x;
    if (qid >= (size_t)T_ * 8192) return;
    int t    = (int)(qid >> 13);
    int rem  = (int)(qid & 8191);
    int ku   = rem >> 7;
    int mgrp = (rem >> 5) & 3;
    int lane = rem & 31;
    int grp = lane >> 2, tig = lane & 3;
    int b0 = mgrp * 16 + grp;
    int k0 = ku * 16 + 2 * tig;
    const float* x0 = x + ((size_t)b0 * T_ + t) * D_;
    const float* x1 = x + ((size_t)(b0 + 8) * T_ + t) * D_;
    uint4 q;
    q.x = pack2(x0[k0],     x0[k0 + 1]);
    q.y = pack2(x1[k0],     x1[k0 + 1]);
    q.z = pack2(x0[k0 + 8], x0[k0 + 9]);
    q.w = pack2(x1[k0 + 8], x1[k0 + 9]);
    g_xtq[qid] = q;
}

__global__ void k_pack_bq(const float* __restrict__ W, const float* __restrict__ R) {
    int qid = blockIdx.x * 256 + threadIdx.x;
    if (qid >= NB_ * 8192) return;
    int bk  = qid >> 13;
    int rem = qid & 8191;
    int ku2 = rem >> 7;
    int col = (rem >> 2) & 31;
    int tig = rem & 3;
    int sc = (bk == NUB_) ? col : 32 + (col >> 3) * 1024 + bk * 8 + (col & 7);
    const float* M = (ku2 < 32) ? W : R;
    int kb = (ku2 & 31) * 32 + 2 * tig;
    const float* Mc = M + sc;
    uint4 q;
    q.x = pack2(Mc[(size_t)(kb)      * G_], Mc[(size_t)(kb + 1)  * G_]);
    q.y = pack2(Mc[(size_t)(kb + 8)  * G_], Mc[(size_t)(kb + 9)  * G_]);
    q.z = pack2(Mc[(size_t)(kb + 16) * G_], Mc[(size_t)(kb + 17) * G_]);
    q.w = pack2(Mc[(size_t)(kb + 24) * G_], Mc[(size_t)(kb + 25) * G_]);
    g_bq[qid] = q;
}

__global__ void k_zero() {
    int i = blockIdx.x * blockDim.x + threadIdx.x;
    if (i < 8192) g_hq[0][i] = make_uint4(0u, 0u, 0u, 0u);
    if (i == 0) { g_ctr = 0u; g_mflag = 0u; }
}

// ---------------- fused persistent kernel -------------------------------------
// 129 blocks x 256 threads. z_t = [x_t, h_{t-1}] @ [W;R] + bias, K=2048.
// 8 warps = 2 m32n32 tiles x 4-way K-split; two-wave smem partial reduction.
// smem: Bs 8192u4 | As 2x2048u4 | zs 64xZSTf | red 1024 float4 | bs 32f
__global__ __launch_bounds__(256, 1) void k_rec(float* __restrict__ out,
                                                const float* __restrict__ bias) {
    extern __shared__ uint4 sm4[];
    uint4*  Bs   = sm4;                          // 8192
    uint4*  As   = sm4 + 8192;                   // 2 x 2048
    float*  zs   = (float*)(sm4 + 8192 + 4096);  // 64 x ZST
    float4* red4 = (float4*)(zs + 64 * ZST);     // 1024 float4 (4 slots x 256)
    float*  bs   = (float*)(red4 + 1024);        // 32

    const int tid  = threadIdx.x;
    const int bk   = blockIdx.x;
    const int warp = tid >> 5, lane = tid & 31;
    const int grp  = lane >> 2, tig = lane & 3;
    const int tile = warp & 1;                   // m-half: rows tile*32..+31
    const int ks   = warp >> 1;                  // k-group 0..3
    const int u0   = bk * 8;
    const int lvl  = bk >> 3;
    const bool master = (bk == NUB_);

    // epilogue mapping (tid < 128) + register cell state
    const int ebg = tid >> 5, eln = tid & 31;
    const int egp = eln >> 2, etg = eln & 3;
    const int er  = ebg * 16 + egp;
    const int ej0 = 2 * etg;
    float creg[4] = {0.f, 0.f, 0.f, 0.f};

    // one-time: [W;R] frags -> smem, bias
    {
        const uint4* bsrc = g_bq + (size_t)bk * 8192;
        #pragma unroll
        for (int r = 0; r < 32; r++) cp16(Bs + tid + r * 256, bsrc + tid + r * 256);
        cpcommit(); cpwait<0>();
        if (tid < 32) {
            int sc = master ? tid : 32 + (tid >> 3) * 1024 + bk * 8 + (tid & 7);
            bs[tid] = bias[sc];
        }
        __syncthreads();
    }

    // bootstrap: x chunks 0,1 of t=0
    {
        const uint4* xsrc = g_xtq;
        #pragma unroll
        for (int r = 0; r < 8; r++) cp16(As + tid + r * 256, xsrc + tid + r * 256);
        cpcommit();
        #pragma unroll
        for (int r = 0; r < 8; r++) cp16(As + 2048 + tid + r * 256, xsrc + 2048 + tid + r * 256);
        cpcommit();
    }

    for (int t = 0; t < T_; ++t) {
        const uint4* xnext = g_xtq + (size_t)(t + 1) * 8192;
        const uint4* hsrc  = g_hq[t & 1];

        float acc[2][4][4];
        #pragma unroll
        for (int a = 0; a < 2; a++)
            #pragma unroll
            for (int b = 0; b < 4; b++)
                #pragma unroll
                for (int c = 0; c < 4; c++) acc[a][b][c] = 0.f;

        #pragma unroll 1
        for (int c = 0; c < 8; ++c) {
            if (c == 7 && t == T_ - 1) cpwait<0>(); else cpwait<1>();
            __syncthreads();
            const uint4* A = As + (c & 1) * 2048;
            #pragma unroll
            for (int kk = 0; kk < 2; ++kk) {
                int k32l = ks * 2 + kk;
                int ku2  = c * 8 + k32l;
                uint4 bq0 = Bs[ku2 * 128 + 0 * 32 + lane];
                uint4 bq1 = Bs[ku2 * 128 + 1 * 32 + lane];
                uint4 bq2 = Bs[ku2 * 128 + 2 * 32 + lane];
                uint4 bq3 = Bs[ku2 * 128 + 3 * 32 + lane];
                #pragma unroll
                for (int mt = 0; mt < 2; ++mt) {
                    uint4 aE = A[(k32l * 2)     * 128 + (tile * 2 + mt) * 32 + lane];
                    uint4 aO = A[(k32l * 2 + 1) * 128 + (tile * 2 + mt) * 32 + lane];
                    mma_f16(acc[mt][0], aE.x, aE.y, aE.z, aE.w, bq0.x, bq0.y);
                    mma_f16(acc[mt][0], aO.x, aO.y, aO.z, aO.w, bq0.z, bq0.w);
                    mma_f16(acc[mt][1], aE.x, aE.y, aE.z, aE.w, bq1.x, bq1.y);
                    mma_f16(acc[mt][1], aO.x, aO.y, aO.z, aO.w, bq1.z, bq1.w);
                    mma_f16(acc[mt][2], aE.x, aE.y, aE.z, aE.w, bq2.x, bq2.y);
                    mma_f16(acc[mt][2], aO.x, aO.y, aO.z, aO.w, bq2.z, bq2.w);
                    mma_f16(acc[mt][3], aE.x, aE.y, aE.z, aE.w, bq3.x, bq3.y);
                    mma_f16(acc[mt][3], aO.x, aO.y, aO.z, aO.w, bq3.z, bq3.w);
                }
            }
            // h-ready gate: must pass before issuing chunk 4 (first h chunk)
            if (c == 2 && tid == 0) {
                unsigned target = 129u * (unsigned)t;
                while (*(volatile unsigned*)&g_ctr < target) __nanosleep(32);
            }
            __syncthreads();
            // issue chunk c+2: 2,3 = x(t); 4..7 = h(t); 8,9 = x(t+1) prefetch
            int nc = c + 2;
            const uint4* src = nullptr;
            if (nc < 4)            src = g_xtq + (size_t)t * 8192 + nc * 2048;
            else if (nc < 8)       src = hsrc + (nc - 4) * 2048;
            else if (t + 1 < T_)   src = xnext + (nc - 8) * 2048;
            if (src) {
                uint4* dst = As + (nc & 1) * 2048;
                #pragma unroll
                for (int r = 0; r < 8; r++) cp16(dst + tid + r * 256, src + tid + r * 256);
                cpcommit();
            }
        }

        // master: h reads complete -> arrive on ctr early (no data to publish)
        if (master && tid == 0) atomicAdd(&g_ctr, 1u);

        // ---- two-wave K-split reduction ----
        if (warp >= 4) {
            int slot = warp - 4;
            #pragma unroll
            for (int q = 0; q < 8; q++) {
                int mt = q >> 2, nt = q & 3;
                red4[slot * 256 + q * 32 + lane] =
                    make_float4(acc[mt][nt][0], acc[mt][nt][1], acc[mt][nt][2], acc[mt][nt][3]);
            }
        }
        __syncthreads();
        if (warp < 4) {
            int slot = warp;
            #pragma unroll
            for (int q = 0; q < 8; q++) {
                int mt = q >> 2, nt = q & 3;
                float4 p = red4[slot * 256 + q * 32 + lane];
                acc[mt][nt][0] += p.x; acc[mt][nt][1] += p.y;
                acc[mt][nt][2] += p.z; acc[mt][nt][3] += p.w;
            }
        }
        __syncthreads();
        if (warp == 2 || warp == 3) {
            int slot = warp - 2;
            #pragma unroll
            for (int q = 0; q < 8; q++) {
                int mt = q >> 2, nt = q & 3;
                red4[slot * 256 + q * 32 + lane] =
                    make_float4(acc[mt][nt][0], acc[mt][nt][1], acc[mt][nt][2], acc[mt][nt][3]);
            }
        }
        __syncthreads();
        if (warp < 2) {
            int slot = warp;
            #pragma unroll
            for (int q = 0; q < 8; q++) {
                int mt = q >> 2, nt = q & 3;
                float4 p = red4[slot * 256 + q * 32 + lane];
                acc[mt][nt][0] += p.x; acc[mt][nt][1] += p.y;
                acc[mt][nt][2] += p.z; acc[mt][nt][3] += p.w;
            }
            // z = acc + bias -> zs
            #pragma unroll
            for (int mt = 0; mt < 2; mt++) {
                int r0 = tile * 32 + mt * 16 + grp;
                #pragma unroll
                for (int nt = 0; nt < 4; nt++) {
                    int c0 = nt * 8 + tig * 2;
                    float bv0 = bs[c0], bv1 = bs[c0 + 1];
                    zs[r0 * ZST + c0]           = acc[mt][nt][0] + bv0;
                    zs[r0 * ZST + c0 + 1]       = acc[mt][nt][1] + bv1;
                    zs[(r0 + 8) * ZST + c0]     = acc[mt][nt][2] + bv0;
                    zs[(r0 + 8) * ZST + c0 + 1] = acc[mt][nt][3] + bv1;
                }
            }
        }
        __syncthreads();   // zs published

        if (master) {
            if (tid < 128) {
                int b = tid >> 1, half = tid & 1;
                const float* lz = zs + b * ZST + half * 16;
                float v[16], mx = -1e30f;
                #pragma unroll
                for (int i = 0; i < 16; i++) { v[i] = lz[i]; mx = fmaxf(mx, v[i]); }
                float s = 0.f;
                #pragma unroll
                for (int i = 0; i < 16; i++) { v[i] = expf(v[i] - mx); s += v[i]; }
                float inv = 1.f / s;
                if (half == 0) {
                    float run = 0.f;
                    #pragma unroll
                    for (int i = 0; i < 16; i++) {
                        run += v[i] * inv;
                        __stcg(&g_masters[b * 32 + i], run);
                    }
                } else {
                    float run = 0.f;
                    #pragma unroll
                    for (int i = 15; i >= 0; i--) {
                        run += v[i] * inv;
                        __stcg(&g_masters[b * 32 + 16 + i], run);
                    }
                }
            }
            __threadfence();
            __syncthreads();
            if (tid == 0) *(volatile unsigned*)&g_mflag = (unsigned)(t + 1);
        } else {
            // precompute gates while an idle warp polls the master flag
            float pf[4], pi[4], po[4], pg[4];
            if (tid < 128) {
                #pragma unroll
                for (int e = 0; e < 4; e++) {
                    int row = er + ((e >> 1) ? 8 : 0);
                    int j = ej0 + (e & 1);
                    float fz = zs[row * ZST + j];
                    float iz = zs[row * ZST + 8 + j];
                    float oz = zs[row * ZST + 16 + j];
                    float gz = zs[row * ZST + 24 + j];
                    pf[e] = 1.f / (1.f + expf(-fz));
                    pi[e] = 1.f / (1.f + expf(-iz));
                    po[e] = 1.f / (1.f + expf(-oz));
                    pg[e] = tanhf(gz);
                }
            } else if (tid == 128) {
                while (*(volatile unsigned*)&g_mflag < (unsigned)(t + 1)) __nanosleep(16);
            }
            __syncthreads();   // masters observed + gates ready

            uint4* hout4 = g_hq[(t + 1) & 1];
            if (tid < 128) {
                float fmA = __ldcg(&g_masters[er * 32 + lvl]);
                float imA = __ldcg(&g_masters[er * 32 + 16 + lvl]);
                float fmB = __ldcg(&g_masters[(er + 8) * 32 + lvl]);
                float imB = __ldcg(&g_masters[(er + 8) * 32 + 16 + lvl]);
                float hv[4];
                #pragma unroll
                for (int e = 0; e < 4; e++) {
                    float fm = (e >> 1) ? fmB : fmA;
                    float im = (e >> 1) ? imB : imA;
                    float w = fm * im;
                    float c = w * (pf[e] * creg[e] + pi[e] * pg[e])
                            + (fm - w) * creg[e] + (im - w) * pg[e];
                    creg[e] = c;
                    hv[e] = po[e] * tanhf(c);
                }
                int row0 = er, row1 = er + 8;
                float2 o0 = make_float2(hv[0], hv[1]);
                float2 o1 = make_float2(hv[2], hv[3]);
                *(float2*)&out[((size_t)row0 * T_ + t) * U_ + u0 + ej0] = o0;
                *(float2*)&out[((size_t)row1 * T_ + t) * U_ + u0 + ej0] = o1;
                unsigned w0 = pack2(hv[0], hv[1]);
                unsigned w1 = pack2(hv[2], hv[3]);
                char* dst = (char*)(hout4 + (bk >> 1) * 128 + ebg * 32 + eln) + (bk & 1) * 8;
                asm volatile("st.global.cg.v2.u32 [%0], {%1,%2};"
                             :: "l"(dst), "r"(w0), "r"(w1) : "memory");
            }
            __threadfence();
            __syncthreads();
            if (tid == 0) atomicAdd(&g_ctr, 1u);
        }
    }
}

// ---------------- entry -------------------------------------------------------
extern "C" void kernel_launch(void* const* d_in, const int* in_sizes, int n_in,
                              void* d_out, int out_size) {
    const float* x    = (const float*)d_in[0];
    const float* W    = (const float*)d_in[1];
    const float* R    = (const float*)d_in[2];
    const float* bias = (const float*)d_in[3];
    float* out = (float*)d_out;

    // smem: 131072 (Bs) + 65536 (As) + 17408 (zs) + 16384 (red) + 128 (bs) = 230528
    cudaFuncSetAttribute(k_rec, cudaFuncAttributeMaxDynamicSharedMemorySize, 230528);

    k_pack_aq<<<(int)(((size_t)T_ * 8192 + 255) / 256), 256>>>(x);
    k_pack_bq<<<(NB_ * 8192 + 255) / 256, 256>>>(W, R);
    k_zero<<<32, 256>>>();
    k_rec<<<NB_, 256, 230528>>>(out, bias);
}

// round 15
// speedup vs baseline: 1.7595x; 1.2295x over previous
#include <cuda_runtime.h>
#include <cuda_fp16.h>
#include <cstdint>
#include <cstddef>

#define B_     64
#define T_     512
#define D_     1024
#define U_     1024
#define G_     4128
#define NUB_   128          // unit blocks
#define NB_    129          // + 1 master block
#define ZST    68

// ---------------- static device scratch (no allocation APIs) ----------------
__device__ __align__(256) uint4 g_xtq[(size_t)T_ * 8192]; // x A-frag quads, per-step
__device__ __align__(256) uint4 g_bq[(size_t)NB_ * 8192]; // [W;R] B-frag quads per block
__device__ __align__(256) uint4 g_hq[2][8192];            // h A-frag quads, ping-pong
__device__ __align__(256) float g_masters[B_ * 32];
__device__ unsigned g_ctr;
__device__ unsigned g_mflag;

// ---------------- helpers ----------------------------------------------------
__device__ __forceinline__ unsigned pack2(float lo, float hi) {
    __half2 h = __floats2half2_rn(lo, hi);
    return *reinterpret_cast<unsigned*>(&h);
}
__device__ __forceinline__ void mma_f16(float c[4], unsigned a0, unsigned a1,
                                        unsigned a2, unsigned a3,
                                        unsigned b0, unsigned b1) {
    asm volatile(
        "mma.sync.aligned.m16n8k16.row.col.f32.f16.f16.f32 "
        "{%0,%1,%2,%3},{%4,%5,%6,%7},{%8,%9},{%0,%1,%2,%3};"
        : "+f"(c[0]), "+f"(c[1]), "+f"(c[2]), "+f"(c[3])
        : "r"(a0), "r"(a1), "r"(a2), "r"(a3), "r"(b0), "r"(b1));
}
__device__ __forceinline__ void cp16(void* s, const void* g) {
    unsigned a = (unsigned)__cvta_generic_to_shared(s);
    asm volatile("cp.async.cg.shared.global [%0], [%1], 16;" :: "r"(a), "l"(g));
}
__device__ __forceinline__ void cpcommit() { asm volatile("cp.async.commit_group;"); }
template<int N> __device__ __forceinline__ void cpwait() {
    asm volatile("cp.async.wait_group %0;" :: "n"(N));
}

// ---------------- prepack kernels (layouts identical to R14) ------------------
__global__ void k_pack_aq(const float* __restrict__ x) {
    size_t qid = (size_t)blockIdx.x * 256 + threadIdx.x;
    if (qid >= (size_t)T_ * 8192) return;
    int t    = (int)(qid >> 13);
    int rem  = (int)(qid & 8191);
    int ku   = rem >> 7;
    int mgrp = (rem >> 5) & 3;
    int lane = rem & 31;
    int grp = lane >> 2, tig = lane & 3;
    int b0 = mgrp * 16 + grp;
    int k0 = ku * 16 + 2 * tig;
    const float* x0 = x + ((size_t)b0 * T_ + t) * D_;
    const float* x1 = x + ((size_t)(b0 + 8) * T_ + t) * D_;
    uint4 q;
    q.x = pack2(x0[k0],     x0[k0 + 1]);
    q.y = pack2(x1[k0],     x1[k0 + 1]);
    q.z = pack2(x0[k0 + 8], x0[k0 + 9]);
    q.w = pack2(x1[k0 + 8], x1[k0 + 9]);
    g_xtq[qid] = q;
}

__global__ void k_pack_bq(const float* __restrict__ W, const float* __restrict__ R) {
    int qid = blockIdx.x * 256 + threadIdx.x;
    if (qid >= NB_ * 8192) return;
    int bk  = qid >> 13;
    int rem = qid & 8191;
    int ku2 = rem >> 7;
    int col = (rem >> 2) & 31;
    int tig = rem & 3;
    int sc = (bk == NUB_) ? col : 32 + (col >> 3) * 1024 + bk * 8 + (col & 7);
    const float* M = (ku2 < 32) ? W : R;
    int kb = (ku2 & 31) * 32 + 2 * tig;
    const float* Mc = M + sc;
    uint4 q;
    q.x = pack2(Mc[(size_t)(kb)      * G_], Mc[(size_t)(kb + 1)  * G_]);
    q.y = pack2(Mc[(size_t)(kb + 8)  * G_], Mc[(size_t)(kb + 9)  * G_]);
    q.z = pack2(Mc[(size_t)(kb + 16) * G_], Mc[(size_t)(kb + 17) * G_]);
    q.w = pack2(Mc[(size_t)(kb + 24) * G_], Mc[(size_t)(kb + 25) * G_]);
    g_bq[qid] = q;
}

__global__ void k_zero() {
    int i = blockIdx.x * blockDim.x + threadIdx.x;
    if (i < 8192) g_hq[0][i] = make_uint4(0u, 0u, 0u, 0u);
    if (i == 0) { g_ctr = 0u; g_mflag = 0u; }
}

// ---------------- fused persistent kernel -------------------------------------
// 129 blocks x 256 threads. z_t = [x_t, h_{t-1}] @ [W;R] + bias, K=2048.
// A operand streamed global->registers (__ldcg), double-buffered; no smem A,
// no barriers inside GEMM. B resident in smem. 2 m32n32 tiles x 4-way K-split.
// smem: Bs 8192u4 (128KB) | zs 64xZSTf | red 1024 float4 | bs 32f  = ~161KB
__global__ __launch_bounds__(256, 1) void k_rec(float* __restrict__ out,
                                                const float* __restrict__ bias) {
    extern __shared__ uint4 sm4[];
    uint4*  Bs   = sm4;                          // 8192
    float*  zs   = (float*)(sm4 + 8192);         // 64 x ZST
    float4* red4 = (float4*)(zs + 64 * ZST);     // 1024 float4
    float*  bs   = (float*)(red4 + 1024);        // 32

    const int tid  = threadIdx.x;
    const int bk   = blockIdx.x;
    const int warp = tid >> 5, lane = tid & 31;
    const int grp  = lane >> 2, tig = lane & 3;
    const int tile = warp & 1;                   // m-half: rows tile*32..+31
    const int ks   = warp >> 1;                  // k-group 0..3
    const int u0   = bk * 8;
    const int lvl  = bk >> 3;
    const bool master = (bk == NUB_);

    // epilogue mapping (tid < 128) + register cell state
    const int ebg = tid >> 5, eln = tid & 31;
    const int egp = eln >> 2, etg = eln & 3;
    const int er  = ebg * 16 + egp;
    const int ej0 = 2 * etg;
    float creg[4] = {0.f, 0.f, 0.f, 0.f};

    // per-warp A base offset within a chunk (ku-local, mgroup, lane)
    const int aoff0 = (ks * 2 * 2) * 128 + (tile * 2) * 32 + lane;   // kk=0,par=0,mt=0

    // one-time: [W;R] frags -> smem, bias
    {
        const uint4* bsrc = g_bq + (size_t)bk * 8192;
        #pragma unroll
        for (int r = 0; r < 32; r++) cp16(Bs + tid + r * 256, bsrc + tid + r * 256);
        cpcommit(); cpwait<0>();
        if (tid < 32) {
            int sc = master ? tid : 32 + (tid >> 3) * 1024 + bk * 8 + (tid & 7);
            bs[tid] = bias[sc];
        }
        __syncthreads();
    }

    uint4 areg0[8], areg1[8];

    // issue 8 A quads for one chunk: idx = kk*4 + par*2 + mt
    auto issue8 = [&](const uint4* cb, uint4* dst) {
        #pragma unroll
        for (int kk = 0; kk < 2; kk++)
            #pragma unroll
            for (int par = 0; par < 2; par++)
                #pragma unroll
                for (int mt = 0; mt < 2; mt++)
                    dst[kk * 4 + par * 2 + mt] =
                        __ldcg(cb + aoff0 + (kk * 2 + par) * 128 + mt * 32);
    };

    // bootstrap: chunk 0 of t=0 (x, no dependency)
    issue8(g_xtq, areg0);

    for (int t = 0; t < T_; ++t) {
        const uint4* xcur = g_xtq + (size_t)t * 8192;
        const uint4* xnxt = xcur + 8192;
        const uint4* hsrc = g_hq[t & 1];

        float acc[2][4][4];
        #pragma unroll
        for (int a = 0; a < 2; a++)
            #pragma unroll
            for (int b = 0; b < 4; b++)
                #pragma unroll
                for (int c = 0; c < 4; c++) acc[a][b][c] = 0.f;

        #pragma unroll
        for (int c = 0; c < 8; ++c) {
            uint4* cur = (c & 1) ? areg1 : areg0;
            uint4* nxt = (c & 1) ? areg0 : areg1;

            // h-ready gate before first h-chunk issue (per-warp, no block barrier)
            if (c == 3) {
                if (lane == 0) {
                    unsigned target = 129u * (unsigned)t;
                    while (*(volatile unsigned*)&g_ctr < target) __nanosleep(64);
                }
                __syncwarp();
            }
            // issue chunk c+1 (c<3: x(t); 3..6: h(t); 7: x(t+1) chunk 0)
            if (c < 3)      issue8(xcur + (c + 1) * 2048, nxt);
            else if (c < 7) issue8(hsrc + (c - 3) * 2048, nxt);
            else if (t + 1 < T_) issue8(xnxt, nxt);

            // compute chunk c from registers + Bs
            #pragma unroll
            for (int kk = 0; kk < 2; ++kk) {
                int ku2 = c * 8 + ks * 2 + kk;
                uint4 bq0 = Bs[ku2 * 128 + 0 * 32 + lane];
                uint4 bq1 = Bs[ku2 * 128 + 1 * 32 + lane];
                uint4 bq2 = Bs[ku2 * 128 + 2 * 32 + lane];
                uint4 bq3 = Bs[ku2 * 128 + 3 * 32 + lane];
                #pragma unroll
                for (int mt = 0; mt < 2; ++mt) {
                    uint4 aE = cur[kk * 4 + 0 * 2 + mt];
                    uint4 aO = cur[kk * 4 + 1 * 2 + mt];
                    mma_f16(acc[mt][0], aE.x, aE.y, aE.z, aE.w, bq0.x, bq0.y);
                    mma_f16(acc[mt][0], aO.x, aO.y, aO.z, aO.w, bq0.z, bq0.w);
                    mma_f16(acc[mt][1], aE.x, aE.y, aE.z, aE.w, bq1.x, bq1.y);
                    mma_f16(acc[mt][1], aO.x, aO.y, aO.z, aO.w, bq1.z, bq1.w);
                    mma_f16(acc[mt][2], aE.x, aE.y, aE.z, aE.w, bq2.x, bq2.y);
                    mma_f16(acc[mt][2], aO.x, aO.y, aO.z, aO.w, bq2.z, bq2.w);
                    mma_f16(acc[mt][3], aE.x, aE.y, aE.z, aE.w, bq3.x, bq3.y);
                    mma_f16(acc[mt][3], aO.x, aO.y, aO.z, aO.w, bq3.z, bq3.w);
                }
            }
        }

        // master: h reads complete -> arrive on ctr early
        if (master && tid == 0) atomicAdd(&g_ctr, 1u);

        // ---- two-wave K-split reduction ----
        __syncthreads();
        if (warp >= 4) {
            int slot = warp - 4;
            #pragma unroll
            for (int q = 0; q < 8; q++) {
                int mt = q >> 2, nt = q & 3;
                red4[slot * 256 + q * 32 + lane] =
                    make_float4(acc[mt][nt][0], acc[mt][nt][1], acc[mt][nt][2], acc[mt][nt][3]);
            }
        }
        __syncthreads();
        if (warp < 4) {
            int slot = warp;
            #pragma unroll
            for (int q = 0; q < 8; q++) {
                int mt = q >> 2, nt = q & 3;
                float4 p = red4[slot * 256 + q * 32 + lane];
                acc[mt][nt][0] += p.x; acc[mt][nt][1] += p.y;
                acc[mt][nt][2] += p.z; acc[mt][nt][3] += p.w;
            }
        }
        __syncthreads();
        if (warp == 2 || warp == 3) {
            int slot = warp - 2;
            #pragma unroll
            for (int q = 0; q < 8; q++) {
                int mt = q >> 2, nt = q & 3;
                red4[slot * 256 + q * 32 + lane] =
                    make_float4(acc[mt][nt][0], acc[mt][nt][1], acc[mt][nt][2], acc[mt][nt][3]);
            }
        }
        __syncthreads();
        if (warp < 2) {
            int slot = warp;
            #pragma unroll
            for (int q = 0; q < 8; q++) {
                int mt = q >> 2, nt = q & 3;
                float4 p = red4[slot * 256 + q * 32 + lane];
                acc[mt][nt][0] += p.x; acc[mt][nt][1] += p.y;
                acc[mt][nt][2] += p.z; acc[mt][nt][3] += p.w;
            }
            #pragma unroll
            for (int mt = 0; mt < 2; mt++) {
                int r0 = tile * 32 + mt * 16 + grp;
                #pragma unroll
                for (int nt = 0; nt < 4; nt++) {
                    int c0 = nt * 8 + tig * 2;
                    float bv0 = bs[c0], bv1 = bs[c0 + 1];
                    zs[r0 * ZST + c0]           = acc[mt][nt][0] + bv0;
                    zs[r0 * ZST + c0 + 1]       = acc[mt][nt][1] + bv1;
                    zs[(r0 + 8) * ZST + c0]     = acc[mt][nt][2] + bv0;
                    zs[(r0 + 8) * ZST + c0 + 1] = acc[mt][nt][3] + bv1;
                }
            }
        }
        __syncthreads();   // zs published

        if (master) {
            if (tid < 128) {
                int b = tid >> 1, half = tid & 1;
                const float* lz = zs + b * ZST + half * 16;
                float v[16], mx = -1e30f;
                #pragma unroll
                for (int i = 0; i < 16; i++) { v[i] = lz[i]; mx = fmaxf(mx, v[i]); }
                float s = 0.f;
                #pragma unroll
                for (int i = 0; i < 16; i++) { v[i] = expf(v[i] - mx); s += v[i]; }
                float inv = 1.f / s;
                if (half == 0) {
                    float run = 0.f;
                    #pragma unroll
                    for (int i = 0; i < 16; i++) {
                        run += v[i] * inv;
                        __stcg(&g_masters[b * 32 + i], run);
                    }
                } else {
                    float run = 0.f;
                    #pragma unroll
                    for (int i = 15; i >= 0; i--) {
                        run += v[i] * inv;
                        __stcg(&g_masters[b * 32 + 16 + i], run);
                    }
                }
            }
            __threadfence();
            __syncthreads();
            if (tid == 0) *(volatile unsigned*)&g_mflag = (unsigned)(t + 1);
        } else {
            // precompute gates while an idle warp polls the master flag
            float pf[4], pi[4], po[4], pg[4];
            if (tid < 128) {
                #pragma unroll
                for (int e = 0; e < 4; e++) {
                    int row = er + ((e >> 1) ? 8 : 0);
                    int j = ej0 + (e & 1);
                    float fz = zs[row * ZST + j];
                    float iz = zs[row * ZST + 8 + j];
                    float oz = zs[row * ZST + 16 + j];
                    float gz = zs[row * ZST + 24 + j];
                    pf[e] = 1.f / (1.f + expf(-fz));
                    pi[e] = 1.f / (1.f + expf(-iz));
                    po[e] = 1.f / (1.f + expf(-oz));
                    pg[e] = tanhf(gz);
                }
            } else if (tid == 128) {
                while (*(volatile unsigned*)&g_mflag < (unsigned)(t + 1)) __nanosleep(16);
            }
            __syncthreads();   // masters observed + gates ready

            uint4* hout4 = g_hq[(t + 1) & 1];
            if (tid < 128) {
                float fmA = __ldcg(&g_masters[er * 32 + lvl]);
                float imA = __ldcg(&g_masters[er * 32 + 16 + lvl]);
                float fmB = __ldcg(&g_masters[(er + 8) * 32 + lvl]);
                float imB = __ldcg(&g_masters[(er + 8) * 32 + 16 + lvl]);
                float hv[4];
                #pragma unroll
                for (int e = 0; e < 4; e++) {
                    float fm = (e >> 1) ? fmB : fmA;
                    float im = (e >> 1) ? imB : imA;
                    float w = fm * im;
                    float c = w * (pf[e] * creg[e] + pi[e] * pg[e])
                            + (fm - w) * creg[e] + (im - w) * pg[e];
                    creg[e] = c;
                    hv[e] = po[e] * tanhf(c);
                }
                float2 o0 = make_float2(hv[0], hv[1]);
                float2 o1 = make_float2(hv[2], hv[3]);
                *(float2*)&out[((size_t)er * T_ + t) * U_ + u0 + ej0] = o0;
                *(float2*)&out[((size_t)(er + 8) * T_ + t) * U_ + u0 + ej0] = o1;
                unsigned w0 = pack2(hv[0], hv[1]);
                unsigned w1 = pack2(hv[2], hv[3]);
                char* dst = (char*)(hout4 + (bk >> 1) * 128 + ebg * 32 + eln) + (bk & 1) * 8;
                asm volatile("st.global.cg.v2.u32 [%0], {%1,%2};"
                             :: "l"(dst), "r"(w0), "r"(w1) : "memory");
            }
            __threadfence();
            __syncthreads();
            if (tid == 0) atomicAdd(&g_ctr, 1u);
        }
    }
}

// ---------------- entry -------------------------------------------------------
extern "C" void kernel_launch(void* const* d_in, const int* in_sizes, int n_in,
                              void* d_out, int out_size) {
    const float* x    = (const float*)d_in[0];
    const float* W    = (const float*)d_in[1];
    const float* R    = (const float*)d_in[2];
    const float* bias = (const float*)d_in[3];
    float* out = (float*)d_out;

    // smem: 131072 (Bs) + 17408 (zs) + 16384 (red) + 128 (bs) = 164992
    cudaFuncSetAttribute(k_rec, cudaFuncAttributeMaxDynamicSharedMemorySize, 164992);

    k_pack_aq<<<(int)(((size_t)T_ * 8192 + 255) / 256), 256>>>(x);
    k_pack_bq<<<(NB_ * 8192 + 255) / 256, 256>>>(W, R);
    k_zero<<<32, 256>>>();
    k_rec<<<NB_, 256, 164992>>>(out, bias);
}